// round 15
// baseline (speedup 1.0000x reference)
#include <cuda_runtime.h>
#include <cuda_bf16.h>
#include <cstdint>

#define T_PTS 524288
#define B_GR  1024
#define NC    10

typedef unsigned long long u64;

// staging buffers
__device__ float g_w[2 * T_PTS];         // per-point sigmoid weights
__device__ float g_X[B_GR * 128];        // pooled features (v0 | v1)
__device__ int   g_segs[2][B_GR + 1];    // segment bounds per branch

__device__ __forceinline__ uint32_t pack_bf16x2(float lowv, float highv) {
    uint32_t r;
    asm("cvt.rn.bf16x2.f32 %0, %1, %2;" : "=r"(r) : "f"(highv), "f"(lowv));
    return r;
}

// -------------------------------------------------------------------------
// Kernel S: segment bounds from sorted batch ids.
// -------------------------------------------------------------------------
__global__ __launch_bounds__(256) void seg_bounds_kernel(
    const int* __restrict__ batch0, const int* __restrict__ batch1)
{
    const int i  = blockIdx.x * 256 + threadIdx.x;
    const int br = blockIdx.y;
    if (i >= T_PTS) return;
    const int* b = br ? batch1 : batch0;
    int* s = g_segs[br];
    const int cur  = b[i];
    const int prev = (i == 0) ? -1 : b[i - 1];
    for (int g = prev + 1; g <= cur; g++) s[g] = i;
    if (i == T_PTS - 1)
        for (int g = cur + 1; g <= B_GR; g++) s[g] = T_PTS;
}

// -------------------------------------------------------------------------
// Kernel W: weight MLP, bf16 m16n8k16 mma.sync. 16-point warp tiles:
// acc shrinks to [8][4] = 32 regs -> ~80 regs total -> 3 blocks/SM
// (occupancy +50% vs the 32-pt tile). Layer-1 in packed bf16x2.
// -------------------------------------------------------------------------
__global__ __launch_bounds__(256, 3) void weight_mlp_mma(
    const float* __restrict__ diag0, const float* __restrict__ diag1,
    const float* __restrict__ Ww0, const float* __restrict__ bw0,
    const float* __restrict__ Ww1, const float* __restrict__ bw1,
    const float* __restrict__ Wwo, const float* __restrict__ bwo)
{
    __shared__ __align__(16) u64   sBf[1024];   // [kt*8+nt][lane] = {b0,b1}
    __shared__ __align__(16) uint4 sCp[32];     // k-pair: {w0x2, w0y2, b2, -}
    __shared__ __align__(8)  float sB1[64];     // layer-2 bias
    __shared__ __align__(8)  float sWo[64];     // output weights

    const int tid  = threadIdx.x;
    const int lane = tid & 31;
    const int wrp  = tid >> 5;
    const int tig  = lane & 3;
    const int gid  = lane >> 2;

    for (int e = tid; e < 1024; e += 256) {
        const int combo = e >> 5, ln = e & 31;
        const int kt = combo >> 3, nt = combo & 7;
        const int tg = ln & 3, gd = ln >> 2;
        const int k0 = kt * 16 + 2 * tg;
        const int n  = nt * 8 + gd;
        const uint32_t lo = pack_bf16x2(Ww1[k0 * 64 + n],       Ww1[(k0 + 1) * 64 + n]);
        const uint32_t hi = pack_bf16x2(Ww1[(k0 + 8) * 64 + n], Ww1[(k0 + 9) * 64 + n]);
        sBf[e] = ((u64)hi << 32) | (u64)lo;
    }
    if (tid < 32) {
        const int k = 2 * tid;
        sCp[tid] = make_uint4(
            pack_bf16x2(Ww0[k],      Ww0[k + 1]),        // W0x pair
            pack_bf16x2(Ww0[64 + k], Ww0[64 + k + 1]),   // W0y pair
            pack_bf16x2(bw0[k],      bw0[k + 1]),        // bias pair
            0u);
    }
    if (tid < 64) {
        sB1[tid] = bw1[tid];
        sWo[tid] = Wwo[tid];
    }
    const float bwo0 = bwo[0];
    __syncthreads();

    const int branch = blockIdx.x >> 9;
    const float2* p2 = (const float2*)(branch ? diag1 : diag0);
    float* wout      = g_w + branch * T_PTS;
    const int wbase  = (blockIdx.x & 511) * 1024 + wrp * 128;

#pragma unroll 1
    for (int t = 0; t < 8; t++) {
        const int tbase = wbase + t * 16;
        const float2 p  = p2[tbase + (lane & 15)];

        uint32_t pxx2[2], pyy2[2];
#pragma unroll
        for (int m = 0; m < 2; m++) {
            const float px = __shfl_sync(0xffffffffu, p.x, gid + 8 * m);
            const float py = __shfl_sync(0xffffffffu, p.y, gid + 8 * m);
            pxx2[m] = pack_bf16x2(px, px);
            pyy2[m] = pack_bf16x2(py, py);
        }

        // acc init = layer-2 bias (c0,c1: pt gid; c2,c3: pt gid+8)
        float acc[8][4];
#pragma unroll
        for (int nt = 0; nt < 8; nt++) {
            const float2 bb = *(const float2*)&sB1[nt * 8 + 2 * tig];
            acc[nt][0] = bb.x; acc[nt][1] = bb.y;
            acc[nt][2] = bb.x; acc[nt][3] = bb.y;
        }

#pragma unroll
        for (int kt = 0; kt < 4; kt++) {
            const uint4 cl = sCp[kt * 8 + tig];       // k-pair ka, ka+1
            const uint4 ch = sCp[kt * 8 + 4 + tig];   // k-pair ka+8, ka+9
            uint32_t a0, a1, a2, a3;
            {
                uint32_t tl, th;
                // m = 0 (row gid)
                asm("fma.rn.bf16x2 %0, %1, %2, %3;"
                    : "=r"(tl) : "r"(pyy2[0]), "r"(cl.y), "r"(cl.z));
                asm("fma.rn.bf16x2 %0, %1, %2, %3;"
                    : "=r"(tl) : "r"(pxx2[0]), "r"(cl.x), "r"(tl));
                asm("max.bf16x2 %0, %1, %2;" : "=r"(a0) : "r"(tl), "r"(0u));
                asm("fma.rn.bf16x2 %0, %1, %2, %3;"
                    : "=r"(th) : "r"(pyy2[0]), "r"(ch.y), "r"(ch.z));
                asm("fma.rn.bf16x2 %0, %1, %2, %3;"
                    : "=r"(th) : "r"(pxx2[0]), "r"(ch.x), "r"(th));
                asm("max.bf16x2 %0, %1, %2;" : "=r"(a2) : "r"(th), "r"(0u));
                // m = 1 (row gid+8)
                asm("fma.rn.bf16x2 %0, %1, %2, %3;"
                    : "=r"(tl) : "r"(pyy2[1]), "r"(cl.y), "r"(cl.z));
                asm("fma.rn.bf16x2 %0, %1, %2, %3;"
                    : "=r"(tl) : "r"(pxx2[1]), "r"(cl.x), "r"(tl));
                asm("max.bf16x2 %0, %1, %2;" : "=r"(a1) : "r"(tl), "r"(0u));
                asm("fma.rn.bf16x2 %0, %1, %2, %3;"
                    : "=r"(th) : "r"(pyy2[1]), "r"(ch.y), "r"(ch.z));
                asm("fma.rn.bf16x2 %0, %1, %2, %3;"
                    : "=r"(th) : "r"(pxx2[1]), "r"(ch.x), "r"(th));
                asm("max.bf16x2 %0, %1, %2;" : "=r"(a3) : "r"(th), "r"(0u));
            }
#pragma unroll
            for (int nt = 0; nt < 8; nt++) {
                const u64 bu = sBf[(kt * 8 + nt) * 32 + lane];
                const uint32_t b0 = (uint32_t)bu, b1 = (uint32_t)(bu >> 32);
                asm volatile(
                    "mma.sync.aligned.m16n8k16.row.col.f32.bf16.bf16.f32 "
                    "{%0,%1,%2,%3}, {%4,%5,%6,%7}, {%8,%9}, {%0,%1,%2,%3};"
                    : "+f"(acc[nt][0]), "+f"(acc[nt][1]),
                      "+f"(acc[nt][2]), "+f"(acc[nt][3])
                    : "r"(a0), "r"(a1), "r"(a2), "r"(a3),
                      "r"(b0), "r"(b1));
            }
        }

        // ---- epilogue: s0 (pt gid), s1 (pt gid+8) ----
        float s0 = 0.f, s1 = 0.f;
#pragma unroll
        for (int nt = 0; nt < 8; nt++) {
            const float2 wo = *(const float2*)&sWo[nt * 8 + 2 * tig];
            s0 = fmaf(fmaxf(acc[nt][0], 0.f), wo.x, s0);
            s0 = fmaf(fmaxf(acc[nt][1], 0.f), wo.y, s0);
            s1 = fmaf(fmaxf(acc[nt][2], 0.f), wo.x, s1);
            s1 = fmaf(fmaxf(acc[nt][3], 0.f), wo.y, s1);
        }
        s0 += __shfl_xor_sync(0xffffffffu, s0, 1);
        s0 += __shfl_xor_sync(0xffffffffu, s0, 2);
        s1 += __shfl_xor_sync(0xffffffffu, s1, 1);
        s1 += __shfl_xor_sync(0xffffffffu, s1, 2);

        if (tig == 0) {
            float e0, r0, e1, r1;
            asm("ex2.approx.f32 %0, %1;" : "=f"(e0)
                : "f"(-1.4426950408889634f * (s0 + bwo0)));
            asm("rcp.approx.f32 %0, %1;" : "=f"(r0) : "f"(1.f + e0));
            asm("ex2.approx.f32 %0, %1;" : "=f"(e1)
                : "f"(-1.4426950408889634f * (s1 + bwo0)));
            asm("rcp.approx.f32 %0, %1;" : "=f"(r1) : "f"(1.f + e1));
            wout[tbase + gid]     = r0;
            wout[tbase + gid + 8] = r1;
        }
    }
}

// -------------------------------------------------------------------------
// Kernel G: gaussian rep + weighted pooling, q-per-lane, seg bounds from
// g_segs (r8 version, fp32 ex2).
// -------------------------------------------------------------------------
__global__ __launch_bounds__(128) void gauss_pool_kernel(
    const float* __restrict__ diag0, const float* __restrict__ diag1,
    const float* __restrict__ theta)
{
    __shared__ __align__(16) float4 sP[4][32];
    __shared__ float sRed[4][64];

    const int bid    = blockIdx.x;
    const int branch = bid >> 10;
    const int g      = bid & (B_GR - 1);
    const int tid    = threadIdx.x;
    const int lane   = tid & 31, wrp = tid >> 5;
    const float2* p2  = (const float2*)(branch ? diag1 : diag0);
    const float* wbuf = g_w + branch * T_PTS;

    const float K2 = -72.13475204444817f;   // -50 * log2(e)  (sigma=0.1)
    const float M2 = 144.26950408889634f;   // +100 * log2(e)
    const float2 t0 = ((const float2*)theta)[lane];
    const float2 t1 = ((const float2*)theta)[lane + 32];
    const float gx0 = M2 * t0.x, gy0 = M2 * t0.y;
    const float ga0 = K2 * fmaf(t0.x, t0.x, t0.y * t0.y);
    const float gx1 = M2 * t1.x, gy1 = M2 * t1.y;
    const float ga1 = K2 * fmaf(t1.x, t1.x, t1.y * t1.y);

    const int start = g_segs[branch][g];
    const int end   = g_segs[branch][g + 1];

    float acc0 = 0.f, acc1 = 0.f;

    for (int base = start + wrp * 32; base < end; base += 128) {
        const int n = min(32, end - base);
        float2 p = make_float2(0.f, 0.f);
        float  w = 0.f;
        if (lane < n) { p = p2[base + lane]; w = wbuf[base + lane]; }
        sP[wrp][lane] = make_float4(p.x, p.y,
                                    K2 * fmaf(p.x, p.x, p.y * p.y), w);
        __syncwarp();

        if (n == 32) {
#pragma unroll 8
            for (int j = 0; j < 32; j++) {
                const float4 q = sP[wrp][j];
                float a0 = fmaf(q.x, gx0, fmaf(q.y, gy0, ga0 + q.z));
                float a1 = fmaf(q.x, gx1, fmaf(q.y, gy1, ga1 + q.z));
                float r0, r1;
                asm("ex2.approx.f32 %0, %1;" : "=f"(r0) : "f"(a0));
                asm("ex2.approx.f32 %0, %1;" : "=f"(r1) : "f"(a1));
                acc0 = fmaf(q.w, r0, acc0);
                acc1 = fmaf(q.w, r1, acc1);
            }
        } else {
            for (int j = 0; j < n; j++) {
                const float4 q = sP[wrp][j];
                float a0 = fmaf(q.x, gx0, fmaf(q.y, gy0, ga0 + q.z));
                float a1 = fmaf(q.x, gx1, fmaf(q.y, gy1, ga1 + q.z));
                float r0, r1;
                asm("ex2.approx.f32 %0, %1;" : "=f"(r0) : "f"(a0));
                asm("ex2.approx.f32 %0, %1;" : "=f"(r1) : "f"(a1));
                acc0 = fmaf(q.w, r0, acc0);
                acc1 = fmaf(q.w, r1, acc1);
            }
        }
        __syncwarp();
    }

    sRed[wrp][lane]      = acc0;
    sRed[wrp][lane + 32] = acc1;
    __syncthreads();
    if (tid < 64)
        g_X[g * 128 + branch * 64 + tid]
            = sRed[0][tid] + sRed[1][tid] + sRed[2][tid] + sRed[3][tid];
}

// -------------------------------------------------------------------------
// Kernel B: final MLP, 8 graphs/block, all weights staged in smem (r8 ver).
// -------------------------------------------------------------------------
#define FB_GPB 8
#define OFF_W0   0
#define OFF_W1   18432
#define OFF_WRO  34816
#define OFF_B0   36096
#define OFF_B1   36224
#define OFF_BRO  36352
#define OFF_XT   36368
#define OFF_HT   37520
#define OFF_H2T  38544
#define FB_SMEM_FLOATS 39568

__global__ __launch_bounds__(256) void final_mlp_kernel(
    const float* __restrict__ gf,
    const float* __restrict__ Wr0, const float* __restrict__ br0,
    const float* __restrict__ Wr1, const float* __restrict__ br1,
    const float* __restrict__ Wro, const float* __restrict__ bro,
    float* __restrict__ out)
{
    extern __shared__ __align__(16) float sm[];
    const int tid = threadIdx.x;
    const int g0  = blockIdx.x * FB_GPB;

    {
        float4* d = (float4*)(sm + OFF_W0);
        const float4* s = (const float4*)Wr0;
        for (int i = tid; i < 18432 / 4; i += 256) d[i] = s[i];
    }
    {
        float4* d = (float4*)(sm + OFF_W1);
        const float4* s = (const float4*)Wr1;
        for (int i = tid; i < 16384 / 4; i += 256) d[i] = s[i];
    }
    {
        float4* d = (float4*)(sm + OFF_WRO);
        const float4* s = (const float4*)Wro;
        for (int i = tid; i < 1280 / 4; i += 256) d[i] = s[i];
    }
    if (tid < 128) {
        sm[OFF_B0 + tid] = br0[tid];
        sm[OFF_B1 + tid] = br1[tid];
    }
    if (tid < NC) sm[OFF_BRO + tid] = bro[tid];

    for (int idx = tid; idx < 144 * FB_GPB; idx += 256) {
        const int i = idx >> 3, g = idx & 7;
        sm[OFF_XT + i * 8 + g] = (i < 128)
            ? g_X[(g0 + g) * 128 + i]
            : gf[(g0 + g) * 16 + (i - 128)];
    }
    __syncthreads();

    const int col   = tid & 127;
    const int gslot = tid >> 7;

    {
        float a0 = sm[OFF_B0 + col], a1 = a0, a2 = a0, a3 = a0;
        const float* w = sm + OFF_W0 + col;
        const float* x = sm + OFF_XT + gslot * 4;
#pragma unroll 4
        for (int i = 0; i < 144; i++) {
            const float4 xv = *(const float4*)(x + i * 8);
            const float wv = w[i * 128];
            a0 = fmaf(xv.x, wv, a0); a1 = fmaf(xv.y, wv, a1);
            a2 = fmaf(xv.z, wv, a2); a3 = fmaf(xv.w, wv, a3);
        }
        *(float4*)(sm + OFF_HT + col * 8 + gslot * 4) =
            make_float4(fmaxf(a0, 0.f), fmaxf(a1, 0.f),
                        fmaxf(a2, 0.f), fmaxf(a3, 0.f));
    }
    __syncthreads();

    {
        float a0 = sm[OFF_B1 + col], a1 = a0, a2 = a0, a3 = a0;
        const float* w = sm + OFF_W1 + col;
        const float* x = sm + OFF_HT + gslot * 4;
#pragma unroll 4
        for (int i = 0; i < 128; i++) {
            const float4 xv = *(const float4*)(x + i * 8);
            const float wv = w[i * 128];
            a0 = fmaf(xv.x, wv, a0); a1 = fmaf(xv.y, wv, a1);
            a2 = fmaf(xv.z, wv, a2); a3 = fmaf(xv.w, wv, a3);
        }
        *(float4*)(sm + OFF_H2T + col * 8 + gslot * 4) =
            make_float4(fmaxf(a0, 0.f), fmaxf(a1, 0.f),
                        fmaxf(a2, 0.f), fmaxf(a3, 0.f));
    }
    __syncthreads();

    if (tid < FB_GPB * NC) {
        const int g = tid / NC, c = tid - g * NC;
        float a = sm[OFF_BRO + c];
        const float* x = sm + OFF_H2T + g;
        const float* w = sm + OFF_WRO + c;
#pragma unroll 8
        for (int k = 0; k < 128; k++)
            a = fmaf(x[k * 8], w[k * NC], a);
        out[(g0 + g) * NC + c] = a;
    }
}

// -------------------------------------------------------------------------
extern "C" void kernel_launch(void* const* d_in, const int* in_sizes, int n_in,
                              void* d_out, int out_size)
{
    const float* diag0 = (const float*)d_in[0];
    const float* diag1 = (const float*)d_in[1];
    const float* gf    = (const float*)d_in[2];
    const float* theta = (const float*)d_in[3];
    const float* Ww0   = (const float*)d_in[4];
    const float* bw0   = (const float*)d_in[5];
    const float* Ww1   = (const float*)d_in[6];
    const float* bw1   = (const float*)d_in[7];
    const float* Wwo   = (const float*)d_in[8];
    const float* bwo   = (const float*)d_in[9];
    const float* Wr0   = (const float*)d_in[10];
    const float* br0   = (const float*)d_in[11];
    const float* Wr1   = (const float*)d_in[12];
    const float* br1   = (const float*)d_in[13];
    const float* Wro   = (const float*)d_in[14];
    const float* bro   = (const float*)d_in[15];
    const int*   batch0 = (const int*)d_in[16];
    const int*   batch1 = (const int*)d_in[17];

    const int fb_smem = FB_SMEM_FLOATS * (int)sizeof(float);
    static int attr_set = 0;
    if (!attr_set) {
        cudaFuncSetAttribute(final_mlp_kernel,
                             cudaFuncAttributeMaxDynamicSharedMemorySize,
                             fb_smem);
        attr_set = 1;
    }

    dim3 sgrid((T_PTS + 255) / 256, 2);
    seg_bounds_kernel<<<sgrid, 256>>>(batch0, batch1);
    weight_mlp_mma<<<1024, 256>>>(diag0, diag1,
                                  Ww0, bw0, Ww1, bw1, Wwo, bwo);
    gauss_pool_kernel<<<2 * B_GR, 128>>>(diag0, diag1, theta);
    final_mlp_kernel<<<B_GR / FB_GPB, 256, fb_smem>>>(
        gf, Wr0, br0, Wr1, br1, Wro, bro, (float*)d_out);
}

// round 16
// speedup vs baseline: 1.0531x; 1.0531x over previous
#include <cuda_runtime.h>
#include <cuda_bf16.h>
#include <cstdint>

#define T_PTS 524288
#define B_GR  1024
#define NC    10

typedef unsigned long long u64;

// staging buffers
__device__ float g_w[2 * T_PTS];         // per-point sigmoid weights
__device__ float g_X[B_GR * 128];        // pooled features (v0 | v1)
__device__ int   g_segs[2][B_GR + 1];    // segment bounds per branch

__device__ __forceinline__ uint32_t pack_bf16x2(float lowv, float highv) {
    uint32_t r;
    asm("cvt.rn.bf16x2.f32 %0, %1, %2;" : "=r"(r) : "f"(highv), "f"(lowv));
    return r;
}

// -------------------------------------------------------------------------
// Kernel W: weight MLP, bf16 m16n8k16 mma.sync (r14 champion: 32-pt tiles,
// packed-bf16x2 layer-1) with two additions:
//  - blocks >= 1024 run the seg-bounds scan (the old seg kernel) and exit,
//    removing one launch from the graph.
//  - B fragments stored as nt-pairs (uint4) -> LDS.128, halving B-frag
//    load instructions.
// -------------------------------------------------------------------------
__global__ __launch_bounds__(256) void weight_mlp_mma(
    const float* __restrict__ diag0, const float* __restrict__ diag1,
    const int* __restrict__ batch0, const int* __restrict__ batch1,
    const float* __restrict__ Ww0, const float* __restrict__ bw0,
    const float* __restrict__ Ww1, const float* __restrict__ bw1,
    const float* __restrict__ Wwo, const float* __restrict__ bwo)
{
    // ---- seg-bounds blocks (appended to the grid) ----
    if (blockIdx.x >= 1024) {
        const int sb = blockIdx.x - 1024;        // 0..4095
        const int br = sb >> 11;                 // 2048 blocks per branch
        const int i  = (sb & 2047) * 256 + threadIdx.x;
        if (i < T_PTS) {
            const int* b = br ? batch1 : batch0;
            int* s = g_segs[br];
            const int cur  = b[i];
            const int prev = (i == 0) ? -1 : b[i - 1];
            for (int g = prev + 1; g <= cur; g++) s[g] = i;
            if (i == T_PTS - 1)
                for (int g = cur + 1; g <= B_GR; g++) s[g] = T_PTS;
        }
        return;
    }

    __shared__ __align__(16) uint4 sBf[512];    // [kt*4+np][lane]: nt pair
    __shared__ __align__(16) uint4 sCp[32];     // k-pair: {w0x2, w0y2, b2, -}
    __shared__ __align__(8)  float sB1[64];     // layer-2 bias
    __shared__ __align__(8)  float sWo[64];     // output weights

    const int tid  = threadIdx.x;
    const int lane = tid & 31;
    const int wrp  = tid >> 5;
    const int tig  = lane & 3;
    const int gid  = lane >> 2;

    // stage B fragments: entry (kt, np, lane) packs nt=2np and nt=2np+1
    for (int e = tid; e < 512; e += 256) {
        const int combo = e >> 5, ln = e & 31;
        const int kt = combo >> 2, np = combo & 3;
        const int tg = ln & 3, gd = ln >> 2;
        const int k0 = kt * 16 + 2 * tg;
        const int ne = (2 * np) * 8 + gd;
        const int no = (2 * np + 1) * 8 + gd;
        sBf[e] = make_uint4(
            pack_bf16x2(Ww1[k0 * 64 + ne],       Ww1[(k0 + 1) * 64 + ne]),
            pack_bf16x2(Ww1[(k0 + 8) * 64 + ne], Ww1[(k0 + 9) * 64 + ne]),
            pack_bf16x2(Ww1[k0 * 64 + no],       Ww1[(k0 + 1) * 64 + no]),
            pack_bf16x2(Ww1[(k0 + 8) * 64 + no], Ww1[(k0 + 9) * 64 + no]));
    }
    if (tid < 32) {
        const int k = 2 * tid;
        sCp[tid] = make_uint4(
            pack_bf16x2(Ww0[k],      Ww0[k + 1]),        // W0x pair
            pack_bf16x2(Ww0[64 + k], Ww0[64 + k + 1]),   // W0y pair
            pack_bf16x2(bw0[k],      bw0[k + 1]),        // bias pair
            0u);
    }
    if (tid < 64) {
        sB1[tid] = bw1[tid];
        sWo[tid] = Wwo[tid];
    }
    const float bwo0 = bwo[0];
    __syncthreads();

    const int branch = blockIdx.x >> 9;
    const float2* p2 = (const float2*)(branch ? diag1 : diag0);
    float* wout      = g_w + branch * T_PTS;
    const int wbase  = (blockIdx.x & 511) * 1024 + wrp * 128;

#pragma unroll 1
    for (int t = 0; t < 4; t++) {
        const int tbase = wbase + t * 32;
        const float2 p  = p2[tbase + lane];

        uint32_t pxx2[4], pyy2[4];
#pragma unroll
        for (int m = 0; m < 4; m++) {
            const float px = __shfl_sync(0xffffffffu, p.x, gid + 8 * m);
            const float py = __shfl_sync(0xffffffffu, p.y, gid + 8 * m);
            pxx2[m] = pack_bf16x2(px, px);
            pyy2[m] = pack_bf16x2(py, py);
        }

        float acc[2][8][4];
#pragma unroll
        for (int nt = 0; nt < 8; nt++) {
            const float2 bb = *(const float2*)&sB1[nt * 8 + 2 * tig];
#pragma unroll
            for (int mt = 0; mt < 2; mt++) {
                acc[mt][nt][0] = bb.x; acc[mt][nt][1] = bb.y;
                acc[mt][nt][2] = bb.x; acc[mt][nt][3] = bb.y;
            }
        }

#pragma unroll
        for (int kt = 0; kt < 4; kt++) {
            const uint4 cl = sCp[kt * 8 + tig];       // k-pair ka, ka+1
            const uint4 ch = sCp[kt * 8 + 4 + tig];   // k-pair ka+8, ka+9
            uint32_t pLo[4], pHi[4];
#pragma unroll
            for (int m = 0; m < 4; m++) {
                uint32_t tl, th;
                asm("fma.rn.bf16x2 %0, %1, %2, %3;"
                    : "=r"(tl) : "r"(pyy2[m]), "r"(cl.y), "r"(cl.z));
                asm("fma.rn.bf16x2 %0, %1, %2, %3;"
                    : "=r"(tl) : "r"(pxx2[m]), "r"(cl.x), "r"(tl));
                asm("max.bf16x2 %0, %1, %2;"
                    : "=r"(tl) : "r"(tl), "r"(0u));
                asm("fma.rn.bf16x2 %0, %1, %2, %3;"
                    : "=r"(th) : "r"(pyy2[m]), "r"(ch.y), "r"(ch.z));
                asm("fma.rn.bf16x2 %0, %1, %2, %3;"
                    : "=r"(th) : "r"(pxx2[m]), "r"(ch.x), "r"(th));
                asm("max.bf16x2 %0, %1, %2;"
                    : "=r"(th) : "r"(th), "r"(0u));
                pLo[m] = tl;
                pHi[m] = th;
            }
#pragma unroll
            for (int np = 0; np < 4; np++) {
                const uint4 bu = sBf[(kt * 4 + np) * 32 + lane];
                const int nte = 2 * np, nto = 2 * np + 1;
                asm volatile(
                    "mma.sync.aligned.m16n8k16.row.col.f32.bf16.bf16.f32 "
                    "{%0,%1,%2,%3}, {%4,%5,%6,%7}, {%8,%9}, {%0,%1,%2,%3};"
                    : "+f"(acc[0][nte][0]), "+f"(acc[0][nte][1]),
                      "+f"(acc[0][nte][2]), "+f"(acc[0][nte][3])
                    : "r"(pLo[0]), "r"(pLo[1]), "r"(pHi[0]), "r"(pHi[1]),
                      "r"(bu.x), "r"(bu.y));
                asm volatile(
                    "mma.sync.aligned.m16n8k16.row.col.f32.bf16.bf16.f32 "
                    "{%0,%1,%2,%3}, {%4,%5,%6,%7}, {%8,%9}, {%0,%1,%2,%3};"
                    : "+f"(acc[1][nte][0]), "+f"(acc[1][nte][1]),
                      "+f"(acc[1][nte][2]), "+f"(acc[1][nte][3])
                    : "r"(pLo[2]), "r"(pLo[3]), "r"(pHi[2]), "r"(pHi[3]),
                      "r"(bu.x), "r"(bu.y));
                asm volatile(
                    "mma.sync.aligned.m16n8k16.row.col.f32.bf16.bf16.f32 "
                    "{%0,%1,%2,%3}, {%4,%5,%6,%7}, {%8,%9}, {%0,%1,%2,%3};"
                    : "+f"(acc[0][nto][0]), "+f"(acc[0][nto][1]),
                      "+f"(acc[0][nto][2]), "+f"(acc[0][nto][3])
                    : "r"(pLo[0]), "r"(pLo[1]), "r"(pHi[0]), "r"(pHi[1]),
                      "r"(bu.z), "r"(bu.w));
                asm volatile(
                    "mma.sync.aligned.m16n8k16.row.col.f32.bf16.bf16.f32 "
                    "{%0,%1,%2,%3}, {%4,%5,%6,%7}, {%8,%9}, {%0,%1,%2,%3};"
                    : "+f"(acc[1][nto][0]), "+f"(acc[1][nto][1]),
                      "+f"(acc[1][nto][2]), "+f"(acc[1][nto][3])
                    : "r"(pLo[2]), "r"(pLo[3]), "r"(pHi[2]), "r"(pHi[3]),
                      "r"(bu.z), "r"(bu.w));
            }
        }

        float s[4] = {0.f, 0.f, 0.f, 0.f};
#pragma unroll
        for (int nt = 0; nt < 8; nt++) {
            const float2 wo = *(const float2*)&sWo[nt * 8 + 2 * tig];
#pragma unroll
            for (int mt = 0; mt < 2; mt++) {
                s[2*mt]   = fmaf(fmaxf(acc[mt][nt][0], 0.f), wo.x, s[2*mt]);
                s[2*mt]   = fmaf(fmaxf(acc[mt][nt][1], 0.f), wo.y, s[2*mt]);
                s[2*mt+1] = fmaf(fmaxf(acc[mt][nt][2], 0.f), wo.x, s[2*mt+1]);
                s[2*mt+1] = fmaf(fmaxf(acc[mt][nt][3], 0.f), wo.y, s[2*mt+1]);
            }
        }
#pragma unroll
        for (int m = 0; m < 4; m++) {
            s[m] += __shfl_xor_sync(0xffffffffu, s[m], 1);
            s[m] += __shfl_xor_sync(0xffffffffu, s[m], 2);
        }
        const float sv = (tig == 0) ? s[0] : (tig == 1) ? s[1]
                       : (tig == 2) ? s[2] : s[3];
        float e, rc;
        asm("ex2.approx.f32 %0, %1;" : "=f"(e)
            : "f"(-1.4426950408889634f * (sv + bwo0)));
        asm("rcp.approx.f32 %0, %1;" : "=f"(rc) : "f"(1.f + e));
        wout[tbase + gid + 8 * tig] = rc;
    }
}

// -------------------------------------------------------------------------
// Kernel G: gaussian rep + weighted pooling, q-per-lane, seg bounds from
// g_segs (r8 version, fp32 ex2).
// -------------------------------------------------------------------------
__global__ __launch_bounds__(128) void gauss_pool_kernel(
    const float* __restrict__ diag0, const float* __restrict__ diag1,
    const float* __restrict__ theta)
{
    __shared__ __align__(16) float4 sP[4][32];
    __shared__ float sRed[4][64];

    const int bid    = blockIdx.x;
    const int branch = bid >> 10;
    const int g      = bid & (B_GR - 1);
    const int tid    = threadIdx.x;
    const int lane   = tid & 31, wrp = tid >> 5;
    const float2* p2  = (const float2*)(branch ? diag1 : diag0);
    const float* wbuf = g_w + branch * T_PTS;

    const float K2 = -72.13475204444817f;   // -50 * log2(e)  (sigma=0.1)
    const float M2 = 144.26950408889634f;   // +100 * log2(e)
    const float2 t0 = ((const float2*)theta)[lane];
    const float2 t1 = ((const float2*)theta)[lane + 32];
    const float gx0 = M2 * t0.x, gy0 = M2 * t0.y;
    const float ga0 = K2 * fmaf(t0.x, t0.x, t0.y * t0.y);
    const float gx1 = M2 * t1.x, gy1 = M2 * t1.y;
    const float ga1 = K2 * fmaf(t1.x, t1.x, t1.y * t1.y);

    const int start = g_segs[branch][g];
    const int end   = g_segs[branch][g + 1];

    float acc0 = 0.f, acc1 = 0.f;

    for (int base = start + wrp * 32; base < end; base += 128) {
        const int n = min(32, end - base);
        float2 p = make_float2(0.f, 0.f);
        float  w = 0.f;
        if (lane < n) { p = p2[base + lane]; w = wbuf[base + lane]; }
        sP[wrp][lane] = make_float4(p.x, p.y,
                                    K2 * fmaf(p.x, p.x, p.y * p.y), w);
        __syncwarp();

        if (n == 32) {
#pragma unroll 8
            for (int j = 0; j < 32; j++) {
                const float4 q = sP[wrp][j];
                float a0 = fmaf(q.x, gx0, fmaf(q.y, gy0, ga0 + q.z));
                float a1 = fmaf(q.x, gx1, fmaf(q.y, gy1, ga1 + q.z));
                float r0, r1;
                asm("ex2.approx.f32 %0, %1;" : "=f"(r0) : "f"(a0));
                asm("ex2.approx.f32 %0, %1;" : "=f"(r1) : "f"(a1));
                acc0 = fmaf(q.w, r0, acc0);
                acc1 = fmaf(q.w, r1, acc1);
            }
        } else {
            for (int j = 0; j < n; j++) {
                const float4 q = sP[wrp][j];
                float a0 = fmaf(q.x, gx0, fmaf(q.y, gy0, ga0 + q.z));
                float a1 = fmaf(q.x, gx1, fmaf(q.y, gy1, ga1 + q.z));
                float r0, r1;
                asm("ex2.approx.f32 %0, %1;" : "=f"(r0) : "f"(a0));
                asm("ex2.approx.f32 %0, %1;" : "=f"(r1) : "f"(a1));
                acc0 = fmaf(q.w, r0, acc0);
                acc1 = fmaf(q.w, r1, acc1);
            }
        }
        __syncwarp();
    }

    sRed[wrp][lane]      = acc0;
    sRed[wrp][lane + 32] = acc1;
    __syncthreads();
    if (tid < 64)
        g_X[g * 128 + branch * 64 + tid]
            = sRed[0][tid] + sRed[1][tid] + sRed[2][tid] + sRed[3][tid];
}

// -------------------------------------------------------------------------
// Kernel B: final MLP, 8 graphs/block, all weights staged in smem (r8 ver).
// -------------------------------------------------------------------------
#define FB_GPB 8
#define OFF_W0   0
#define OFF_W1   18432
#define OFF_WRO  34816
#define OFF_B0   36096
#define OFF_B1   36224
#define OFF_BRO  36352
#define OFF_XT   36368
#define OFF_HT   37520
#define OFF_H2T  38544
#define FB_SMEM_FLOATS 39568

__global__ __launch_bounds__(256) void final_mlp_kernel(
    const float* __restrict__ gf,
    const float* __restrict__ Wr0, const float* __restrict__ br0,
    const float* __restrict__ Wr1, const float* __restrict__ br1,
    const float* __restrict__ Wro, const float* __restrict__ bro,
    float* __restrict__ out)
{
    extern __shared__ __align__(16) float sm[];
    const int tid = threadIdx.x;
    const int g0  = blockIdx.x * FB_GPB;

    {
        float4* d = (float4*)(sm + OFF_W0);
        const float4* s = (const float4*)Wr0;
        for (int i = tid; i < 18432 / 4; i += 256) d[i] = s[i];
    }
    {
        float4* d = (float4*)(sm + OFF_W1);
        const float4* s = (const float4*)Wr1;
        for (int i = tid; i < 16384 / 4; i += 256) d[i] = s[i];
    }
    {
        float4* d = (float4*)(sm + OFF_WRO);
        const float4* s = (const float4*)Wro;
        for (int i = tid; i < 1280 / 4; i += 256) d[i] = s[i];
    }
    if (tid < 128) {
        sm[OFF_B0 + tid] = br0[tid];
        sm[OFF_B1 + tid] = br1[tid];
    }
    if (tid < NC) sm[OFF_BRO + tid] = bro[tid];

    for (int idx = tid; idx < 144 * FB_GPB; idx += 256) {
        const int i = idx >> 3, g = idx & 7;
        sm[OFF_XT + i * 8 + g] = (i < 128)
            ? g_X[(g0 + g) * 128 + i]
            : gf[(g0 + g) * 16 + (i - 128)];
    }
    __syncthreads();

    const int col   = tid & 127;
    const int gslot = tid >> 7;

    {
        float a0 = sm[OFF_B0 + col], a1 = a0, a2 = a0, a3 = a0;
        const float* w = sm + OFF_W0 + col;
        const float* x = sm + OFF_XT + gslot * 4;
#pragma unroll 4
        for (int i = 0; i < 144; i++) {
            const float4 xv = *(const float4*)(x + i * 8);
            const float wv = w[i * 128];
            a0 = fmaf(xv.x, wv, a0); a1 = fmaf(xv.y, wv, a1);
            a2 = fmaf(xv.z, wv, a2); a3 = fmaf(xv.w, wv, a3);
        }
        *(float4*)(sm + OFF_HT + col * 8 + gslot * 4) =
            make_float4(fmaxf(a0, 0.f), fmaxf(a1, 0.f),
                        fmaxf(a2, 0.f), fmaxf(a3, 0.f));
    }
    __syncthreads();

    {
        float a0 = sm[OFF_B1 + col], a1 = a0, a2 = a0, a3 = a0;
        const float* w = sm + OFF_W1 + col;
        const float* x = sm + OFF_HT + gslot * 4;
#pragma unroll 4
        for (int i = 0; i < 128; i++) {
            const float4 xv = *(const float4*)(x + i * 8);
            const float wv = w[i * 128];
            a0 = fmaf(xv.x, wv, a0); a1 = fmaf(xv.y, wv, a1);
            a2 = fmaf(xv.z, wv, a2); a3 = fmaf(xv.w, wv, a3);
        }
        *(float4*)(sm + OFF_H2T + col * 8 + gslot * 4) =
            make_float4(fmaxf(a0, 0.f), fmaxf(a1, 0.f),
                        fmaxf(a2, 0.f), fmaxf(a3, 0.f));
    }
    __syncthreads();

    if (tid < FB_GPB * NC) {
        const int g = tid / NC, c = tid - g * NC;
        float a = sm[OFF_BRO + c];
        const float* x = sm + OFF_H2T + g;
        const float* w = sm + OFF_WRO + c;
#pragma unroll 8
        for (int k = 0; k < 128; k++)
            a = fmaf(x[k * 8], w[k * NC], a);
        out[(g0 + g) * NC + c] = a;
    }
}

// -------------------------------------------------------------------------
extern "C" void kernel_launch(void* const* d_in, const int* in_sizes, int n_in,
                              void* d_out, int out_size)
{
    const float* diag0 = (const float*)d_in[0];
    const float* diag1 = (const float*)d_in[1];
    const float* gf    = (const float*)d_in[2];
    const float* theta = (const float*)d_in[3];
    const float* Ww0   = (const float*)d_in[4];
    const float* bw0   = (const float*)d_in[5];
    const float* Ww1   = (const float*)d_in[6];
    const float* bw1   = (const float*)d_in[7];
    const float* Wwo   = (const float*)d_in[8];
    const float* bwo   = (const float*)d_in[9];
    const float* Wr0   = (const float*)d_in[10];
    const float* br0   = (const float*)d_in[11];
    const float* Wr1   = (const float*)d_in[12];
    const float* br1   = (const float*)d_in[13];
    const float* Wro   = (const float*)d_in[14];
    const float* bro   = (const float*)d_in[15];
    const int*   batch0 = (const int*)d_in[16];
    const int*   batch1 = (const int*)d_in[17];

    const int fb_smem = FB_SMEM_FLOATS * (int)sizeof(float);
    static int attr_set = 0;
    if (!attr_set) {
        cudaFuncSetAttribute(final_mlp_kernel,
                             cudaFuncAttributeMaxDynamicSharedMemorySize,
                             fb_smem);
        attr_set = 1;
    }

    // grid = 1024 heavy MLP blocks + 4096 seg-bounds blocks
    weight_mlp_mma<<<1024 + 4096, 256>>>(diag0, diag1, batch0, batch1,
                                         Ww0, bw0, Ww1, bw1, Wwo, bwo);
    gauss_pool_kernel<<<2 * B_GR, 128>>>(diag0, diag1, theta);
    final_mlp_kernel<<<B_GR / FB_GPB, 256, fb_smem>>>(
        gf, Wr0, br0, Wr1, br1, Wro, bro, (float*)d_out);
}

// round 17
// speedup vs baseline: 1.0842x; 1.0295x over previous
#include <cuda_runtime.h>
#include <cuda_bf16.h>
#include <cstdint>

#define T_PTS 524288
#define B_GR  1024
#define NC    10

typedef unsigned long long u64;

// staging buffers
__device__ float g_w[2 * T_PTS];         // per-point sigmoid weights
__device__ float g_X[B_GR * 128];        // pooled features (v0 | v1)
__device__ int   g_segs[2][B_GR + 1];    // segment bounds per branch

__device__ __forceinline__ uint32_t pack_f16x2(float lowv, float highv) {
    uint32_t r;
    asm("cvt.rn.f16x2.f32 %0, %1, %2;" : "=r"(r) : "f"(highv), "f"(lowv));
    return r;
}

// -------------------------------------------------------------------------
// Kernel S: segment bounds from sorted batch ids.
// -------------------------------------------------------------------------
__global__ __launch_bounds__(256) void seg_bounds_kernel(
    const int* __restrict__ batch0, const int* __restrict__ batch1)
{
    const int i  = blockIdx.x * 256 + threadIdx.x;
    const int br = blockIdx.y;
    if (i >= T_PTS) return;
    const int* b = br ? batch1 : batch0;
    int* s = g_segs[br];
    const int cur  = b[i];
    const int prev = (i == 0) ? -1 : b[i - 1];
    for (int g = prev + 1; g <= cur; g++) s[g] = i;
    if (i == T_PTS - 1)
        for (int g = cur + 1; g <= B_GR; g++) s[g] = T_PTS;
}

// -------------------------------------------------------------------------
// Kernel W: weight MLP, f16 m16n8k16 mma.sync with f16 ACCUMULATORS:
// acc[2][8][2] packed-half2 regs (32) instead of f32 acc (64) -> lower reg
// pressure -> 3 blocks/SM. Layer-1 in packed f16x2 (10-bit mantissa, better
// than bf16). B fragments staged as nt-pair uint4 (LDS.128).
// -------------------------------------------------------------------------
__global__ __launch_bounds__(256) void weight_mlp_mma(
    const float* __restrict__ diag0, const float* __restrict__ diag1,
    const float* __restrict__ Ww0, const float* __restrict__ bw0,
    const float* __restrict__ Ww1, const float* __restrict__ bw1,
    const float* __restrict__ Wwo, const float* __restrict__ bwo)
{
    __shared__ __align__(16) uint4 sBf[512];    // [kt*4+np][lane]: nt pair
    __shared__ __align__(16) uint4 sCp[32];     // k-pair: {w0x2, w0y2, b2, -}
    __shared__ __align__(8)  float sB1[64];     // layer-2 bias
    __shared__ __align__(8)  float sWo[64];     // output weights

    const int tid  = threadIdx.x;
    const int lane = tid & 31;
    const int wrp  = tid >> 5;
    const int tig  = lane & 3;
    const int gid  = lane >> 2;

    // stage B fragments (f16): entry (kt, np, lane) packs nt=2np and 2np+1
    for (int e = tid; e < 512; e += 256) {
        const int combo = e >> 5, ln = e & 31;
        const int kt = combo >> 2, np = combo & 3;
        const int tg = ln & 3, gd = ln >> 2;
        const int k0 = kt * 16 + 2 * tg;
        const int ne = (2 * np) * 8 + gd;
        const int no = (2 * np + 1) * 8 + gd;
        sBf[e] = make_uint4(
            pack_f16x2(Ww1[k0 * 64 + ne],       Ww1[(k0 + 1) * 64 + ne]),
            pack_f16x2(Ww1[(k0 + 8) * 64 + ne], Ww1[(k0 + 9) * 64 + ne]),
            pack_f16x2(Ww1[k0 * 64 + no],       Ww1[(k0 + 1) * 64 + no]),
            pack_f16x2(Ww1[(k0 + 8) * 64 + no], Ww1[(k0 + 9) * 64 + no]));
    }
    if (tid < 32) {
        const int k = 2 * tid;
        sCp[tid] = make_uint4(
            pack_f16x2(Ww0[k],      Ww0[k + 1]),        // W0x pair
            pack_f16x2(Ww0[64 + k], Ww0[64 + k + 1]),   // W0y pair
            pack_f16x2(bw0[k],      bw0[k + 1]),        // bias pair
            0u);
    }
    if (tid < 64) {
        sB1[tid] = bw1[tid];
        sWo[tid] = Wwo[tid];
    }
    const float bwo0 = bwo[0];
    __syncthreads();

    const int branch = blockIdx.x >> 9;
    const float2* p2 = (const float2*)(branch ? diag1 : diag0);
    float* wout      = g_w + branch * T_PTS;
    const int wbase  = (blockIdx.x & 511) * 1024 + wrp * 128;

#pragma unroll 1
    for (int t = 0; t < 4; t++) {
        const int tbase = wbase + t * 32;
        const float2 p  = p2[tbase + lane];

        uint32_t pxx2[4], pyy2[4];
#pragma unroll
        for (int m = 0; m < 4; m++) {
            const float px = __shfl_sync(0xffffffffu, p.x, gid + 8 * m);
            const float py = __shfl_sync(0xffffffffu, p.y, gid + 8 * m);
            pxx2[m] = pack_f16x2(px, px);
            pyy2[m] = pack_f16x2(py, py);
        }

        // acc init = layer-2 bias (packed half2: {col 2tig, col 2tig+1})
        uint32_t acc[2][8][2];
#pragma unroll
        for (int nt = 0; nt < 8; nt++) {
            const float2 bb = *(const float2*)&sB1[nt * 8 + 2 * tig];
            const uint32_t bb2 = pack_f16x2(bb.x, bb.y);
            acc[0][nt][0] = bb2; acc[0][nt][1] = bb2;
            acc[1][nt][0] = bb2; acc[1][nt][1] = bb2;
        }

#pragma unroll
        for (int kt = 0; kt < 4; kt++) {
            const uint4 cl = sCp[kt * 8 + tig];       // k-pair ka, ka+1
            const uint4 ch = sCp[kt * 8 + 4 + tig];   // k-pair ka+8, ka+9
            uint32_t pLo[4], pHi[4];
#pragma unroll
            for (int m = 0; m < 4; m++) {
                uint32_t tl, th;
                asm("fma.rn.f16x2 %0, %1, %2, %3;"
                    : "=r"(tl) : "r"(pyy2[m]), "r"(cl.y), "r"(cl.z));
                asm("fma.rn.f16x2 %0, %1, %2, %3;"
                    : "=r"(tl) : "r"(pxx2[m]), "r"(cl.x), "r"(tl));
                asm("max.f16x2 %0, %1, %2;"
                    : "=r"(tl) : "r"(tl), "r"(0u));
                asm("fma.rn.f16x2 %0, %1, %2, %3;"
                    : "=r"(th) : "r"(pyy2[m]), "r"(ch.y), "r"(ch.z));
                asm("fma.rn.f16x2 %0, %1, %2, %3;"
                    : "=r"(th) : "r"(pxx2[m]), "r"(ch.x), "r"(th));
                asm("max.f16x2 %0, %1, %2;"
                    : "=r"(th) : "r"(th), "r"(0u));
                pLo[m] = tl;
                pHi[m] = th;
            }
#pragma unroll
            for (int np = 0; np < 4; np++) {
                const uint4 bu = sBf[(kt * 4 + np) * 32 + lane];
                const int nte = 2 * np, nto = 2 * np + 1;
                asm volatile(
                    "mma.sync.aligned.m16n8k16.row.col.f16.f16.f16.f16 "
                    "{%0,%1}, {%2,%3,%4,%5}, {%6,%7}, {%0,%1};"
                    : "+r"(acc[0][nte][0]), "+r"(acc[0][nte][1])
                    : "r"(pLo[0]), "r"(pLo[1]), "r"(pHi[0]), "r"(pHi[1]),
                      "r"(bu.x), "r"(bu.y));
                asm volatile(
                    "mma.sync.aligned.m16n8k16.row.col.f16.f16.f16.f16 "
                    "{%0,%1}, {%2,%3,%4,%5}, {%6,%7}, {%0,%1};"
                    : "+r"(acc[1][nte][0]), "+r"(acc[1][nte][1])
                    : "r"(pLo[2]), "r"(pLo[3]), "r"(pHi[2]), "r"(pHi[3]),
                      "r"(bu.x), "r"(bu.y));
                asm volatile(
                    "mma.sync.aligned.m16n8k16.row.col.f16.f16.f16.f16 "
                    "{%0,%1}, {%2,%3,%4,%5}, {%6,%7}, {%0,%1};"
                    : "+r"(acc[0][nto][0]), "+r"(acc[0][nto][1])
                    : "r"(pLo[0]), "r"(pLo[1]), "r"(pHi[0]), "r"(pHi[1]),
                      "r"(bu.z), "r"(bu.w));
                asm volatile(
                    "mma.sync.aligned.m16n8k16.row.col.f16.f16.f16.f16 "
                    "{%0,%1}, {%2,%3,%4,%5}, {%6,%7}, {%0,%1};"
                    : "+r"(acc[1][nto][0]), "+r"(acc[1][nto][1])
                    : "r"(pLo[2]), "r"(pLo[3]), "r"(pHi[2]), "r"(pHi[3]),
                      "r"(bu.z), "r"(bu.w));
            }
        }

        // ---- epilogue: relu in f16x2, dot in f32 ----
        // acc[mt][nt][0] = pt gid of half mt, cols {2tig, 2tig+1};
        // acc[mt][nt][1] = pt gid+8 of half mt.
        float s[4] = {0.f, 0.f, 0.f, 0.f};
#pragma unroll
        for (int nt = 0; nt < 8; nt++) {
            const float2 wo = *(const float2*)&sWo[nt * 8 + 2 * tig];
#pragma unroll
            for (int mt = 0; mt < 2; mt++) {
#pragma unroll
                for (int rr = 0; rr < 2; rr++) {
                    uint32_t rl;
                    asm("max.f16x2 %0, %1, %2;"
                        : "=r"(rl) : "r"(acc[mt][nt][rr]), "r"(0u));
                    const __half2 h2 = *reinterpret_cast<__half2*>(&rl);
                    const float2 f2 = __half22float2(h2);
                    s[2 * mt + rr] = fmaf(f2.x, wo.x, s[2 * mt + rr]);
                    s[2 * mt + rr] = fmaf(f2.y, wo.y, s[2 * mt + rr]);
                }
            }
        }
#pragma unroll
        for (int m = 0; m < 4; m++) {
            s[m] += __shfl_xor_sync(0xffffffffu, s[m], 1);
            s[m] += __shfl_xor_sync(0xffffffffu, s[m], 2);
        }
        const float sv = (tig == 0) ? s[0] : (tig == 1) ? s[1]
                       : (tig == 2) ? s[2] : s[3];
        float e, rc;
        asm("ex2.approx.f32 %0, %1;" : "=f"(e)
            : "f"(-1.4426950408889634f * (sv + bwo0)));
        asm("rcp.approx.f32 %0, %1;" : "=f"(rc) : "f"(1.f + e));
        wout[tbase + gid + 8 * tig] = rc;
    }
}

// -------------------------------------------------------------------------
// Kernel G: gaussian rep + weighted pooling, q-per-lane, seg bounds from
// g_segs (r8 version, fp32 ex2).
// -------------------------------------------------------------------------
__global__ __launch_bounds__(128) void gauss_pool_kernel(
    const float* __restrict__ diag0, const float* __restrict__ diag1,
    const float* __restrict__ theta)
{
    __shared__ __align__(16) float4 sP[4][32];
    __shared__ float sRed[4][64];

    const int bid    = blockIdx.x;
    const int branch = bid >> 10;
    const int g      = bid & (B_GR - 1);
    const int tid    = threadIdx.x;
    const int lane   = tid & 31, wrp = tid >> 5;
    const float2* p2  = (const float2*)(branch ? diag1 : diag0);
    const float* wbuf = g_w + branch * T_PTS;

    const float K2 = -72.13475204444817f;   // -50 * log2(e)  (sigma=0.1)
    const float M2 = 144.26950408889634f;   // +100 * log2(e)
    const float2 t0 = ((const float2*)theta)[lane];
    const float2 t1 = ((const float2*)theta)[lane + 32];
    const float gx0 = M2 * t0.x, gy0 = M2 * t0.y;
    const float ga0 = K2 * fmaf(t0.x, t0.x, t0.y * t0.y);
    const float gx1 = M2 * t1.x, gy1 = M2 * t1.y;
    const float ga1 = K2 * fmaf(t1.x, t1.x, t1.y * t1.y);

    const int start = g_segs[branch][g];
    const int end   = g_segs[branch][g + 1];

    float acc0 = 0.f, acc1 = 0.f;

    for (int base = start + wrp * 32; base < end; base += 128) {
        const int n = min(32, end - base);
        float2 p = make_float2(0.f, 0.f);
        float  w = 0.f;
        if (lane < n) { p = p2[base + lane]; w = wbuf[base + lane]; }
        sP[wrp][lane] = make_float4(p.x, p.y,
                                    K2 * fmaf(p.x, p.x, p.y * p.y), w);
        __syncwarp();

        if (n == 32) {
#pragma unroll 8
            for (int j = 0; j < 32; j++) {
                const float4 q = sP[wrp][j];
                float a0 = fmaf(q.x, gx0, fmaf(q.y, gy0, ga0 + q.z));
                float a1 = fmaf(q.x, gx1, fmaf(q.y, gy1, ga1 + q.z));
                float r0, r1;
                asm("ex2.approx.f32 %0, %1;" : "=f"(r0) : "f"(a0));
                asm("ex2.approx.f32 %0, %1;" : "=f"(r1) : "f"(a1));
                acc0 = fmaf(q.w, r0, acc0);
                acc1 = fmaf(q.w, r1, acc1);
            }
        } else {
            for (int j = 0; j < n; j++) {
                const float4 q = sP[wrp][j];
                float a0 = fmaf(q.x, gx0, fmaf(q.y, gy0, ga0 + q.z));
                float a1 = fmaf(q.x, gx1, fmaf(q.y, gy1, ga1 + q.z));
                float r0, r1;
                asm("ex2.approx.f32 %0, %1;" : "=f"(r0) : "f"(a0));
                asm("ex2.approx.f32 %0, %1;" : "=f"(r1) : "f"(a1));
                acc0 = fmaf(q.w, r0, acc0);
                acc1 = fmaf(q.w, r1, acc1);
            }
        }
        __syncwarp();
    }

    sRed[wrp][lane]      = acc0;
    sRed[wrp][lane + 32] = acc1;
    __syncthreads();
    if (tid < 64)
        g_X[g * 128 + branch * 64 + tid]
            = sRed[0][tid] + sRed[1][tid] + sRed[2][tid] + sRed[3][tid];
}

// -------------------------------------------------------------------------
// Kernel B: final MLP, 8 graphs/block, all weights staged in smem (r8 ver).
// -------------------------------------------------------------------------
#define FB_GPB 8
#define OFF_W0   0
#define OFF_W1   18432
#define OFF_WRO  34816
#define OFF_B0   36096
#define OFF_B1   36224
#define OFF_BRO  36352
#define OFF_XT   36368
#define OFF_HT   37520
#define OFF_H2T  38544
#define FB_SMEM_FLOATS 39568

__global__ __launch_bounds__(256) void final_mlp_kernel(
    const float* __restrict__ gf,
    const float* __restrict__ Wr0, const float* __restrict__ br0,
    const float* __restrict__ Wr1, const float* __restrict__ br1,
    const float* __restrict__ Wro, const float* __restrict__ bro,
    float* __restrict__ out)
{
    extern __shared__ __align__(16) float sm[];
    const int tid = threadIdx.x;
    const int g0  = blockIdx.x * FB_GPB;

    {
        float4* d = (float4*)(sm + OFF_W0);
        const float4* s = (const float4*)Wr0;
        for (int i = tid; i < 18432 / 4; i += 256) d[i] = s[i];
    }
    {
        float4* d = (float4*)(sm + OFF_W1);
        const float4* s = (const float4*)Wr1;
        for (int i = tid; i < 16384 / 4; i += 256) d[i] = s[i];
    }
    {
        float4* d = (float4*)(sm + OFF_WRO);
        const float4* s = (const float4*)Wro;
        for (int i = tid; i < 1280 / 4; i += 256) d[i] = s[i];
    }
    if (tid < 128) {
        sm[OFF_B0 + tid] = br0[tid];
        sm[OFF_B1 + tid] = br1[tid];
    }
    if (tid < NC) sm[OFF_BRO + tid] = bro[tid];

    for (int idx = tid; idx < 144 * FB_GPB; idx += 256) {
        const int i = idx >> 3, g = idx & 7;
        sm[OFF_XT + i * 8 + g] = (i < 128)
            ? g_X[(g0 + g) * 128 + i]
            : gf[(g0 + g) * 16 + (i - 128)];
    }
    __syncthreads();

    const int col   = tid & 127;
    const int gslot = tid >> 7;

    {
        float a0 = sm[OFF_B0 + col], a1 = a0, a2 = a0, a3 = a0;
        const float* w = sm + OFF_W0 + col;
        const float* x = sm + OFF_XT + gslot * 4;
#pragma unroll 4
        for (int i = 0; i < 144; i++) {
            const float4 xv = *(const float4*)(x + i * 8);
            const float wv = w[i * 128];
            a0 = fmaf(xv.x, wv, a0); a1 = fmaf(xv.y, wv, a1);
            a2 = fmaf(xv.z, wv, a2); a3 = fmaf(xv.w, wv, a3);
        }
        *(float4*)(sm + OFF_HT + col * 8 + gslot * 4) =
            make_float4(fmaxf(a0, 0.f), fmaxf(a1, 0.f),
                        fmaxf(a2, 0.f), fmaxf(a3, 0.f));
    }
    __syncthreads();

    {
        float a0 = sm[OFF_B1 + col], a1 = a0, a2 = a0, a3 = a0;
        const float* w = sm + OFF_W1 + col;
        const float* x = sm + OFF_HT + gslot * 4;
#pragma unroll 4
        for (int i = 0; i < 128; i++) {
            const float4 xv = *(const float4*)(x + i * 8);
            const float wv = w[i * 128];
            a0 = fmaf(xv.x, wv, a0); a1 = fmaf(xv.y, wv, a1);
            a2 = fmaf(xv.z, wv, a2); a3 = fmaf(xv.w, wv, a3);
        }
        *(float4*)(sm + OFF_H2T + col * 8 + gslot * 4) =
            make_float4(fmaxf(a0, 0.f), fmaxf(a1, 0.f),
                        fmaxf(a2, 0.f), fmaxf(a3, 0.f));
    }
    __syncthreads();

    if (tid < FB_GPB * NC) {
        const int g = tid / NC, c = tid - g * NC;
        float a = sm[OFF_BRO + c];
        const float* x = sm + OFF_H2T + g;
        const float* w = sm + OFF_WRO + c;
#pragma unroll 8
        for (int k = 0; k < 128; k++)
            a = fmaf(x[k * 8], w[k * NC], a);
        out[(g0 + g) * NC + c] = a;
    }
}

// -------------------------------------------------------------------------
extern "C" void kernel_launch(void* const* d_in, const int* in_sizes, int n_in,
                              void* d_out, int out_size)
{
    const float* diag0 = (const float*)d_in[0];
    const float* diag1 = (const float*)d_in[1];
    const float* gf    = (const float*)d_in[2];
    const float* theta = (const float*)d_in[3];
    const float* Ww0   = (const float*)d_in[4];
    const float* bw0   = (const float*)d_in[5];
    const float* Ww1   = (const float*)d_in[6];
    const float* bw1   = (const float*)d_in[7];
    const float* Wwo   = (const float*)d_in[8];
    const float* bwo   = (const float*)d_in[9];
    const float* Wr0   = (const float*)d_in[10];
    const float* br0   = (const float*)d_in[11];
    const float* Wr1   = (const float*)d_in[12];
    const float* br1   = (const float*)d_in[13];
    const float* Wro   = (const float*)d_in[14];
    const float* bro   = (const float*)d_in[15];
    const int*   batch0 = (const int*)d_in[16];
    const int*   batch1 = (const int*)d_in[17];

    const int fb_smem = FB_SMEM_FLOATS * (int)sizeof(float);
    static int attr_set = 0;
    if (!attr_set) {
        cudaFuncSetAttribute(final_mlp_kernel,
                             cudaFuncAttributeMaxDynamicSharedMemorySize,
                             fb_smem);
        attr_set = 1;
    }

    dim3 sgrid((T_PTS + 255) / 256, 2);
    seg_bounds_kernel<<<sgrid, 256>>>(batch0, batch1);
    weight_mlp_mma<<<1024, 256>>>(diag0, diag1,
                                  Ww0, bw0, Ww1, bw1, Wwo, bwo);
    gauss_pool_kernel<<<2 * B_GR, 128>>>(diag0, diag1, theta);
    final_mlp_kernel<<<B_GR / FB_GPB, 256, fb_smem>>>(
        gf, Wr0, br0, Wr1, br1, Wro, bro, (float*)d_out);
}